// round 10
// baseline (speedup 1.0000x reference)
#include <cuda_runtime.h>
#include <cuda_bf16.h>
#include <math.h>
#include <stdint.h>

#define T_TOKENS 4096
#define D_DIM    1024
#define E_EXP    8
#define F_DIM    2048
#define TWO_F    4096
#define NPAIR    (T_TOKENS * 2)

#define TM 128
#define TN 128
#define KB 64                     // K elements per stage (64 bf16 = 128B rows, SW128)
#define TILE_BYTES 16384          // 128 rows * 128 B
#define STAGE_BYTES (4 * TILE_BYTES)
#define NSTAGE 3
#define SMEM_BYTES (1024 + NSTAGE * STAGE_BYTES)
#define NTHREADS 256

// ---------------- scratch (device globals; no allocs allowed) ----------------
__device__ int   g_cnt[E_EXP];
__device__ int   g_entries[E_EXP][T_TOKENS];
__device__ float g_wts[T_TOKENS][2];
__device__ __nv_bfloat16 g_xh[T_TOKENS * D_DIM];
__device__ __nv_bfloat16 g_xl[T_TOKENS * D_DIM];
__device__ __nv_bfloat16 g_w1h[(size_t)E_EXP * TWO_F * D_DIM];
__device__ __nv_bfloat16 g_w1l[(size_t)E_EXP * TWO_F * D_DIM];
__device__ __nv_bfloat16 g_w2h[(size_t)E_EXP * D_DIM * F_DIM];
__device__ __nv_bfloat16 g_w2l[(size_t)E_EXP * D_DIM * F_DIM];
__device__ __nv_bfloat16 g_hh[(size_t)NPAIR * F_DIM];
__device__ __nv_bfloat16 g_hl[(size_t)NPAIR * F_DIM];

// ---------------- helpers ----------------
__device__ __forceinline__ uint32_t smem_u32(const void* p) {
    uint32_t a;
    asm("{ .reg .u64 t; cvta.to.shared.u64 t, %1; cvt.u32.u64 %0, t; }" : "=r"(a) : "l"(p));
    return a;
}
__device__ __forceinline__ uint32_t sw128(uint32_t o) { return o ^ ((o >> 3) & 0x70); }

__device__ __forceinline__ void cp16(uint32_t dst, const void* src) {
    asm volatile("cp.async.cg.shared.global [%0], [%1], 16;" :: "r"(dst), "l"(src));
}
#define CP_COMMIT() asm volatile("cp.async.commit_group;" ::: "memory")
#define CP_WAIT(n)  asm volatile("cp.async.wait_group %0;" :: "n"(n) : "memory")

__device__ __forceinline__ void ldsm4(uint32_t* r, uint32_t addr) {
    asm volatile("ldmatrix.sync.aligned.m8n8.x4.shared.b16 {%0,%1,%2,%3}, [%4];"
        : "=r"(r[0]), "=r"(r[1]), "=r"(r[2]), "=r"(r[3]) : "r"(addr));
}
__device__ __forceinline__ void mma16816(float* d, const uint32_t* a, uint32_t b0, uint32_t b1) {
    asm volatile("mma.sync.aligned.m16n8k16.row.col.f32.bf16.bf16.f32 "
        "{%0,%1,%2,%3}, {%4,%5,%6,%7}, {%8,%9}, {%0,%1,%2,%3};"
        : "+f"(d[0]), "+f"(d[1]), "+f"(d[2]), "+f"(d[3])
        : "r"(a[0]), "r"(a[1]), "r"(a[2]), "r"(a[3]), "r"(b0), "r"(b1));
}

// ---------------- kernel 0: zero output + counters ----------------
__global__ void zero_all_kernel(float4* __restrict__ out) {
    int i = blockIdx.x * blockDim.x + threadIdx.x;
    if (i < T_TOKENS * D_DIM / 4) out[i] = make_float4(0.f, 0.f, 0.f, 0.f);
    if (blockIdx.x == 0 && threadIdx.x < E_EXP) g_cnt[threadIdx.x] = 0;
}

// ---------------- conversion: fp32 -> bf16 hi + lo (one launch) ----------------
__device__ __forceinline__ void cvt4(float4 f, uint2& H, uint2& L) {
    __nv_bfloat16 h0 = __float2bfloat16(f.x), h1 = __float2bfloat16(f.y);
    __nv_bfloat16 h2 = __float2bfloat16(f.z), h3 = __float2bfloat16(f.w);
    __nv_bfloat16 l0 = __float2bfloat16(f.x - __bfloat162float(h0));
    __nv_bfloat16 l1 = __float2bfloat16(f.y - __bfloat162float(h1));
    __nv_bfloat16 l2 = __float2bfloat16(f.z - __bfloat162float(h2));
    __nv_bfloat16 l3 = __float2bfloat16(f.w - __bfloat162float(h3));
    H.x = (uint32_t)__bfloat16_as_ushort(h0) | ((uint32_t)__bfloat16_as_ushort(h1) << 16);
    H.y = (uint32_t)__bfloat16_as_ushort(h2) | ((uint32_t)__bfloat16_as_ushort(h3) << 16);
    L.x = (uint32_t)__bfloat16_as_ushort(l0) | ((uint32_t)__bfloat16_as_ushort(l1) << 16);
    L.y = (uint32_t)__bfloat16_as_ushort(l2) | ((uint32_t)__bfloat16_as_ushort(l3) << 16);
}
#define NX4  (T_TOKENS * D_DIM / 4)
#define NW14 (E_EXP * TWO_F * D_DIM / 4)
#define NW24 (E_EXP * D_DIM * F_DIM / 4)
__global__ void cvt_all_kernel(const float4* __restrict__ x,
                               const float4* __restrict__ w1,
                               const float4* __restrict__ w2) {
    int i = blockIdx.x * blockDim.x + threadIdx.x;
    if (i < NW14) {
        uint2 H, L; cvt4(w1[i], H, L);
        ((uint2*)g_w1h)[i] = H; ((uint2*)g_w1l)[i] = L;
    } else if (i < NW14 + NW24) {
        int j = i - NW14;
        uint2 H, L; cvt4(w2[j], H, L);
        ((uint2*)g_w2h)[j] = H; ((uint2*)g_w2l)[j] = L;
    } else if (i < NW14 + NW24 + NX4) {
        int j = i - NW14 - NW24;
        uint2 H, L; cvt4(x[j], H, L);
        ((uint2*)g_xh)[j] = H; ((uint2*)g_xl)[j] = L;
    }
}

// ---------------- kernel 1: gate + top2 + routing ----------------
__global__ void gate_kernel(const float* __restrict__ x, const float* __restrict__ gw) {
    int warp = threadIdx.x >> 5;
    int lane = threadIdx.x & 31;
    int t = blockIdx.x * 4 + warp;
    float acc[8] = {0.f,0.f,0.f,0.f,0.f,0.f,0.f,0.f};
    const float* xr = x + (size_t)t * D_DIM;
    for (int d = lane; d < D_DIM; d += 32) {
        float xv = xr[d];
        const float* g = gw + d * 8;
        #pragma unroll
        for (int e = 0; e < 8; e++) acc[e] += xv * g[e];
    }
    #pragma unroll
    for (int off = 16; off > 0; off >>= 1)
        #pragma unroll
        for (int e = 0; e < 8; e++)
            acc[e] += __shfl_down_sync(0xffffffffu, acc[e], off);
    if (lane == 0) {
        int b0 = 0; float v0 = acc[0];
        #pragma unroll
        for (int e = 1; e < 8; e++) if (acc[e] > v0) { v0 = acc[e]; b0 = e; }
        int b1 = -1; float v1 = -3.4e38f;
        #pragma unroll
        for (int e = 0; e < 8; e++) if (e != b0 && acc[e] > v1) { v1 = acc[e]; b1 = e; }
        float w0 = 1.0f / (1.0f + expf(v1 - v0));
        g_wts[t][0] = w0;
        g_wts[t][1] = 1.0f - w0;
        int p0 = atomicAdd(&g_cnt[b0], 1);
        g_entries[b0][p0] = t * 2 + 0;
        int p1 = atomicAdd(&g_cnt[b1], 1);
        g_entries[b1][p1] = t * 2 + 1;
    }
}

// ---------------- shared GEMM machinery (256 threads, 8 warps, warp tile 64x32) ----------------
// smem: [0..512) s_tok, [512..1024) s_val, tiles at 1024: stage{0..2} x {AH,AL,BH,BL}
__device__ __forceinline__ void stage_load(
    uint32_t sb, int buf, int k0, int tid,
    const int* s_tok, bool a_is_pair,
    const __nv_bfloat16* Ah, const __nv_bfloat16* Al, int lda,
    const __nv_bfloat16* Bh, const __nv_bfloat16* Bl, size_t brow0, int ldb)
{
    uint32_t base = sb + 1024 + buf * STAGE_BYTES;
    #pragma unroll
    for (int ii = 0; ii < 4; ii++) {
        int i = tid + ii * NTHREADS;
        int r = i >> 3, v = i & 7;
        uint32_t dsw = sw128((uint32_t)(r * 128 + v * 16));
        int ts = s_tok[r];
        size_t ar = (size_t)(a_is_pair ? (ts >> 1) : ts) * lda + k0 + v * 8;
        size_t wr = (brow0 + r) * (size_t)ldb + k0 + v * 8;
        cp16(base + 0 * TILE_BYTES + dsw, Ah + ar);
        cp16(base + 1 * TILE_BYTES + dsw, Al + ar);
        cp16(base + 2 * TILE_BYTES + dsw, Bh + wr);
        cp16(base + 3 * TILE_BYTES + dsw, Bl + wr);
    }
    CP_COMMIT();
}

// Fragment set for one k16 step: warp tile 64(M) x 32(N).
// 12 LDSM.x4 (48 regs), 48 MMAs per step, double-buffered across steps.
__device__ __forceinline__ void load_frags(
    uint32_t base, int ks, int wm, int wn, int lane,
    uint32_t ah[4][4], uint32_t al[4][4], uint32_t bh[2][4], uint32_t bl[2][4])
{
    int lrow = lane & 15, lk = (lane >> 4) * 16;
    int kb = ks * 32;
    #pragma unroll
    for (int mt = 0; mt < 4; mt++) {
        uint32_t ro = (uint32_t)((wm * 64 + mt * 16 + lrow) * 128 + kb + lk);
        ldsm4(ah[mt], base + 0 * TILE_BYTES + sw128(ro));
        ldsm4(al[mt], base + 1 * TILE_BYTES + sw128(ro));
    }
    #pragma unroll
    for (int np = 0; np < 2; np++) {
        uint32_t ro = (uint32_t)((wn * 32 + np * 16 + lrow) * 128 + kb + lk);
        ldsm4(bh[np], base + 2 * TILE_BYTES + sw128(ro));
        ldsm4(bl[np], base + 3 * TILE_BYTES + sw128(ro));
    }
}

// Term-major MMA bursts: same-accumulator writes are 16 MMAs apart.
__device__ __forceinline__ void mma_frags(
    float acc[4][4][4],
    uint32_t ah[4][4], uint32_t al[4][4], uint32_t bh[2][4], uint32_t bl[2][4])
{
    // term Ah*Bh
    #pragma unroll
    for (int mt = 0; mt < 4; mt++)
        #pragma unroll
        for (int np = 0; np < 2; np++) {
            mma16816(acc[mt][2*np],   ah[mt], bh[np][0], bh[np][2]);
            mma16816(acc[mt][2*np+1], ah[mt], bh[np][1], bh[np][3]);
        }
    // term Ah*Bl
    #pragma unroll
    for (int mt = 0; mt < 4; mt++)
        #pragma unroll
        for (int np = 0; np < 2; np++) {
            mma16816(acc[mt][2*np],   ah[mt], bl[np][0], bl[np][2]);
            mma16816(acc[mt][2*np+1], ah[mt], bl[np][1], bl[np][3]);
        }
    // term Al*Bh
    #pragma unroll
    for (int mt = 0; mt < 4; mt++)
        #pragma unroll
        for (int np = 0; np < 2; np++) {
            mma16816(acc[mt][2*np],   al[mt], bh[np][0], bh[np][2]);
            mma16816(acc[mt][2*np+1], al[mt], bh[np][1], bh[np][3]);
        }
}

// Full stage: double-buffered fragments; prefetch ks+1 before MMAs of ks.
__device__ __forceinline__ void stage_compute(
    uint32_t sb, int buf, int wm, int wn, int lane, float acc[4][4][4])
{
    uint32_t base = sb + 1024 + buf * STAGE_BYTES;
    uint32_t ah[2][4][4], al[2][4][4], bh[2][2][4], bl[2][2][4];
    load_frags(base, 0, wm, wn, lane, ah[0], al[0], bh[0], bl[0]);
    #pragma unroll
    for (int ks = 0; ks < 4; ks++) {
        int cur = ks & 1, nxt = cur ^ 1;
        if (ks < 3)
            load_frags(base, ks + 1, wm, wn, lane, ah[nxt], al[nxt], bh[nxt], bl[nxt]);
        mma_frags(acc, ah[cur], al[cur], bh[cur], bl[cur]);
    }
}

// ---------------- kernel 2: dense1 (HMMA split-bf16) + swiglu -> h hi/lo ----------------
__global__ __launch_bounds__(NTHREADS, 1) void dense1_mma(const float* __restrict__ b1) {
    int e = blockIdx.z, rt = blockIdx.y, ct = blockIdx.x;
    int n = g_cnt[e];
    if (rt * TM >= n) return;

    extern __shared__ char smem[];
    int* s_tok = (int*)smem;
    int* s_val = (int*)(smem + 512);
    uint32_t sb = smem_u32(smem);
    int tid = threadIdx.x, lane = tid & 31, wid = tid >> 5;
    int wm = wid >> 2, wn = wid & 3;

    if (tid < TM) {
        int rg = rt * TM + tid;
        int cl = rg < n ? rg : n - 1;
        s_tok[tid] = g_entries[e][cl];
        s_val[tid] = rg < n;
    }
    __syncthreads();

    float acc[4][4][4];
    #pragma unroll
    for (int a = 0; a < 4; a++)
        #pragma unroll
        for (int b = 0; b < 4; b++)
            #pragma unroll
            for (int c = 0; c < 4; c++) acc[a][b][c] = 0.f;

    size_t brow0 = (size_t)e * TWO_F + (size_t)ct * TN;
    const int NS = D_DIM / KB;  // 16
    stage_load(sb, 0, 0, tid, s_tok, true, g_xh, g_xl, D_DIM, g_w1h, g_w1l, brow0, D_DIM);
    stage_load(sb, 1, KB, tid, s_tok, true, g_xh, g_xl, D_DIM, g_w1h, g_w1l, brow0, D_DIM);
    for (int s = 0; s < NS; s++) {
        if (s + 1 < NS) { CP_WAIT(1); } else { CP_WAIT(0); }
        __syncthreads();
        if (s + 2 < NS)
            stage_load(sb, (s + 2) % NSTAGE, (s + 2) * KB, tid, s_tok, true,
                       g_xh, g_xl, D_DIM, g_w1h, g_w1l, brow0, D_DIM);
        stage_compute(sb, s % NSTAGE, wm, wn, lane, acc);
    }

    // epilogue: swiglu on (gate, value) adjacent even/odd cols
    #pragma unroll
    for (int mt = 0; mt < 4; mt++) {
        #pragma unroll
        for (int nt = 0; nt < 4; nt++) {
            int c = ct * TN + wn * 32 + nt * 8 + (lane & 3) * 2;
            float bg = b1[e * TWO_F + c];
            float bv = b1[e * TWO_F + c + 1];
            #pragma unroll
            for (int hrow = 0; hrow < 2; hrow++) {
                int r = wm * 64 + mt * 16 + (lane >> 2) + hrow * 8;
                if (!s_val[r]) continue;
                int ts = s_tok[r];
                float gpre = acc[mt][nt][hrow * 2 + 0] + bg;
                float vpre = acc[mt][nt][hrow * 2 + 1] + bv;
                float gg = fminf(gpre, 9.0f);
                float vv = fminf(fmaxf(vpre, -9.0f), 9.0f);
                float h = gg * (1.0f / (1.0f + expf(-1.702f * gg))) * (vv + 1.0f);
                __nv_bfloat16 hh = __float2bfloat16(h);
                __nv_bfloat16 hl = __float2bfloat16(h - __bfloat162float(hh));
                size_t f = (size_t)ts * F_DIM + (c >> 1);
                g_hh[f] = hh;
                g_hl[f] = hl;
            }
        }
    }
}

// ---------------- kernel 3: dense2 (HMMA split-bf16) + bias + scale + atomic combine ----------------
__global__ __launch_bounds__(NTHREADS, 1) void dense2_mma(const float* __restrict__ b2,
                                                          float* __restrict__ out) {
    int e = blockIdx.z, rt = blockIdx.y, ct = blockIdx.x;
    int n = g_cnt[e];
    if (rt * TM >= n) return;

    extern __shared__ char smem[];
    int* s_tok = (int*)smem;
    int* s_val = (int*)(smem + 512);
    uint32_t sb = smem_u32(smem);
    int tid = threadIdx.x, lane = tid & 31, wid = tid >> 5;
    int wm = wid >> 2, wn = wid & 3;

    if (tid < TM) {
        int rg = rt * TM + tid;
        int cl = rg < n ? rg : n - 1;
        s_tok[tid] = g_entries[e][cl];
        s_val[tid] = rg < n;
    }
    __syncthreads();

    float acc[4][4][4];
    #pragma unroll
    for (int a = 0; a < 4; a++)
        #pragma unroll
        for (int b = 0; b < 4; b++)
            #pragma unroll
            for (int c = 0; c < 4; c++) acc[a][b][c] = 0.f;

    size_t brow0 = (size_t)e * D_DIM + (size_t)ct * TN;
    const int NS = F_DIM / KB;  // 32
    stage_load(sb, 0, 0, tid, s_tok, false, g_hh, g_hl, F_DIM, g_w2h, g_w2l, brow0, F_DIM);
    stage_load(sb, 1, KB, tid, s_tok, false, g_hh, g_hl, F_DIM, g_w2h, g_w2l, brow0, F_DIM);
    for (int s = 0; s < NS; s++) {
        if (s + 1 < NS) { CP_WAIT(1); } else { CP_WAIT(0); }
        __syncthreads();
        if (s + 2 < NS)
            stage_load(sb, (s + 2) % NSTAGE, (s + 2) * KB, tid, s_tok, false,
                       g_hh, g_hl, F_DIM, g_w2h, g_w2l, brow0, F_DIM);
        stage_compute(sb, s % NSTAGE, wm, wn, lane, acc);
    }

    // per output element exactly 2 expert contributions; fp32 atomicAdd onto
    // zeroed out is commutative -> deterministic.
    #pragma unroll
    for (int mt = 0; mt < 4; mt++) {
        #pragma unroll
        for (int hrow = 0; hrow < 2; hrow++) {
            int r = wm * 64 + mt * 16 + (lane >> 2) + hrow * 8;
            if (!s_val[r]) continue;
            int ts = s_tok[r];
            float wgt = g_wts[ts >> 1][ts & 1];
            float* yrow = out + (size_t)(ts >> 1) * D_DIM;
            #pragma unroll
            for (int nt = 0; nt < 4; nt++) {
                int c = ct * TN + wn * 32 + nt * 8 + (lane & 3) * 2;
                atomicAdd(yrow + c,     (acc[mt][nt][hrow * 2 + 0] + b2[e * D_DIM + c]) * wgt);
                atomicAdd(yrow + c + 1, (acc[mt][nt][hrow * 2 + 1] + b2[e * D_DIM + c + 1]) * wgt);
            }
        }
    }
}

// ---------------- launch ----------------
extern "C" void kernel_launch(void* const* d_in, const int* in_sizes, int n_in,
                              void* d_out, int out_size) {
    const float* x  = (const float*)d_in[0];
    const float* gw = (const float*)d_in[1];
    const float* w1 = (const float*)d_in[2];
    const float* b1 = (const float*)d_in[3];
    const float* w2 = (const float*)d_in[4];
    const float* b2 = (const float*)d_in[5];
    float* out = (float*)d_out;

    cudaFuncSetAttribute(dense1_mma, cudaFuncAttributeMaxDynamicSharedMemorySize, SMEM_BYTES);
    cudaFuncSetAttribute(dense2_mma, cudaFuncAttributeMaxDynamicSharedMemorySize, SMEM_BYTES);

    zero_all_kernel<<<(T_TOKENS * D_DIM / 4 + 255) / 256, 256>>>((float4*)out);
    cvt_all_kernel<<<(NW14 + NW24 + NX4 + 255) / 256, 256>>>(
        (const float4*)x, (const float4*)w1, (const float4*)w2);
    gate_kernel<<<T_TOKENS / 4, 128>>>(x, gw);
    dense1_mma<<<dim3(TWO_F / TN, T_TOKENS / TM, E_EXP), NTHREADS, SMEM_BYTES>>>(b1);
    dense2_mma<<<dim3(D_DIM / TN, T_TOKENS / TM, E_EXP), NTHREADS, SMEM_BYTES>>>(b2, out);
}

// round 11
// speedup vs baseline: 1.4812x; 1.4812x over previous
#include <cuda_runtime.h>
#include <cuda_fp16.h>
#include <math.h>
#include <stdint.h>

#define T_TOKENS 4096
#define D_DIM    1024
#define E_EXP    8
#define F_DIM    2048
#define TWO_F    4096
#define NPAIR    (T_TOKENS * 2)

#define TM 128
#define TN 128
#define KB 64                     // K elements per stage (64 fp16 = 128B rows, SW128)
#define TILE_BYTES 16384          // 128 rows * 128 B
#define STAGE_BYTES (3 * TILE_BYTES)   // A, Bh, Bl
#define NSTAGE 3
#define SMEM_BYTES (1024 + NSTAGE * STAGE_BYTES)
#define NTHREADS 512

// ---------------- scratch (device globals; no allocs allowed) ----------------
__device__ int   g_cnt[E_EXP];
__device__ int   g_entries[E_EXP][T_TOKENS];
__device__ float g_wts[T_TOKENS][2];
__device__ __half g_xf[(size_t)T_TOKENS * D_DIM];
__device__ __half g_w1h[(size_t)E_EXP * TWO_F * D_DIM];
__device__ __half g_w1l[(size_t)E_EXP * TWO_F * D_DIM];
__device__ __half g_w2h[(size_t)E_EXP * D_DIM * F_DIM];
__device__ __half g_w2l[(size_t)E_EXP * D_DIM * F_DIM];
__device__ __half g_hf[(size_t)NPAIR * F_DIM];

// ---------------- helpers ----------------
__device__ __forceinline__ uint32_t smem_u32(const void* p) {
    uint32_t a;
    asm("{ .reg .u64 t; cvta.to.shared.u64 t, %1; cvt.u32.u64 %0, t; }" : "=r"(a) : "l"(p));
    return a;
}
__device__ __forceinline__ uint32_t sw128(uint32_t o) { return o ^ ((o >> 3) & 0x70); }

__device__ __forceinline__ void cp16(uint32_t dst, const void* src) {
    asm volatile("cp.async.cg.shared.global [%0], [%1], 16;" :: "r"(dst), "l"(src));
}
#define CP_COMMIT() asm volatile("cp.async.commit_group;" ::: "memory")
#define CP_WAIT(n)  asm volatile("cp.async.wait_group %0;" :: "n"(n) : "memory")

__device__ __forceinline__ void ldsm4(uint32_t* r, uint32_t addr) {
    asm volatile("ldmatrix.sync.aligned.m8n8.x4.shared.b16 {%0,%1,%2,%3}, [%4];"
        : "=r"(r[0]), "=r"(r[1]), "=r"(r[2]), "=r"(r[3]) : "r"(addr));
}
__device__ __forceinline__ void mma16816(float* d, const uint32_t* a, uint32_t b0, uint32_t b1) {
    asm volatile("mma.sync.aligned.m16n8k16.row.col.f32.f16.f16.f32 "
        "{%0,%1,%2,%3}, {%4,%5,%6,%7}, {%8,%9}, {%0,%1,%2,%3};"
        : "+f"(d[0]), "+f"(d[1]), "+f"(d[2]), "+f"(d[3])
        : "r"(a[0]), "r"(a[1]), "r"(a[2]), "r"(a[3]), "r"(b0), "r"(b1));
}

// ---------------- kernel 0: zero output + counters ----------------
__global__ void zero_all_kernel(float4* __restrict__ out) {
    int i = blockIdx.x * blockDim.x + threadIdx.x;
    if (i < T_TOKENS * D_DIM / 4) out[i] = make_float4(0.f, 0.f, 0.f, 0.f);
    if (blockIdx.x == 0 && threadIdx.x < E_EXP) g_cnt[threadIdx.x] = 0;
}

// ---------------- conversion ----------------
// weights: fp32 -> fp16 hi + fp16 lo (lo may be subnormal; tensor cores handle it)
__device__ __forceinline__ void cvtw4(float4 f, uint2& H, uint2& L) {
    __half h0 = __float2half_rn(f.x), h1 = __float2half_rn(f.y);
    __half h2 = __float2half_rn(f.z), h3 = __float2half_rn(f.w);
    __half l0 = __float2half_rn(f.x - __half2float(h0));
    __half l1 = __float2half_rn(f.y - __half2float(h1));
    __half l2 = __float2half_rn(f.z - __half2float(h2));
    __half l3 = __float2half_rn(f.w - __half2float(h3));
    H.x = (uint32_t)__half_as_ushort(h0) | ((uint32_t)__half_as_ushort(h1) << 16);
    H.y = (uint32_t)__half_as_ushort(h2) | ((uint32_t)__half_as_ushort(h3) << 16);
    L.x = (uint32_t)__half_as_ushort(l0) | ((uint32_t)__half_as_ushort(l1) << 16);
    L.y = (uint32_t)__half_as_ushort(l2) | ((uint32_t)__half_as_ushort(l3) << 16);
}
#define NX4  (T_TOKENS * D_DIM / 4)
#define NW14 (E_EXP * TWO_F * D_DIM / 4)
#define NW24 (E_EXP * D_DIM * F_DIM / 4)
__global__ void cvt_all_kernel(const float4* __restrict__ x,
                               const float4* __restrict__ w1,
                               const float4* __restrict__ w2) {
    int i = blockIdx.x * blockDim.x + threadIdx.x;
    if (i < NW14) {
        uint2 H, L; cvtw4(w1[i], H, L);
        ((uint2*)g_w1h)[i] = H; ((uint2*)g_w1l)[i] = L;
    } else if (i < NW14 + NW24) {
        int j = i - NW14;
        uint2 H, L; cvtw4(w2[j], H, L);
        ((uint2*)g_w2h)[j] = H; ((uint2*)g_w2l)[j] = L;
    } else if (i < NW14 + NW24 + NX4) {
        int j = i - NW14 - NW24;
        float4 f = x[j];
        uint2 H;
        H.x = (uint32_t)__half_as_ushort(__float2half_rn(f.x)) |
              ((uint32_t)__half_as_ushort(__float2half_rn(f.y)) << 16);
        H.y = (uint32_t)__half_as_ushort(__float2half_rn(f.z)) |
              ((uint32_t)__half_as_ushort(__float2half_rn(f.w)) << 16);
        ((uint2*)g_xf)[j] = H;
    }
}

// ---------------- kernel 1: gate + top2 + routing ----------------
__global__ void gate_kernel(const float* __restrict__ x, const float* __restrict__ gw) {
    int warp = threadIdx.x >> 5;
    int lane = threadIdx.x & 31;
    int t = blockIdx.x * 4 + warp;
    float acc[8] = {0.f,0.f,0.f,0.f,0.f,0.f,0.f,0.f};
    const float* xr = x + (size_t)t * D_DIM;
    for (int d = lane; d < D_DIM; d += 32) {
        float xv = xr[d];
        const float* g = gw + d * 8;
        #pragma unroll
        for (int e = 0; e < 8; e++) acc[e] += xv * g[e];
    }
    #pragma unroll
    for (int off = 16; off > 0; off >>= 1)
        #pragma unroll
        for (int e = 0; e < 8; e++)
            acc[e] += __shfl_down_sync(0xffffffffu, acc[e], off);
    if (lane == 0) {
        int b0 = 0; float v0 = acc[0];
        #pragma unroll
        for (int e = 1; e < 8; e++) if (acc[e] > v0) { v0 = acc[e]; b0 = e; }
        int b1 = -1; float v1 = -3.4e38f;
        #pragma unroll
        for (int e = 0; e < 8; e++) if (e != b0 && acc[e] > v1) { v1 = acc[e]; b1 = e; }
        float w0 = 1.0f / (1.0f + expf(v1 - v0));
        g_wts[t][0] = w0;
        g_wts[t][1] = 1.0f - w0;
        int p0 = atomicAdd(&g_cnt[b0], 1);
        g_entries[b0][p0] = t * 2 + 0;
        int p1 = atomicAdd(&g_cnt[b1], 1);
        g_entries[b1][p1] = t * 2 + 1;
    }
}

// ---------------- shared GEMM machinery (512 threads, 16 warps, warp tile 32x32) ----------------
// smem: [0..512) s_tok, [512..1024) s_val, tiles @1024: stage{0..2} x {A, Bh, Bl}
__device__ __forceinline__ void stage_load(
    uint32_t sb, int buf, int k0, int tid,
    const int* s_tok, bool a_is_pair,
    const __half* A, int lda,
    const __half* Bh, const __half* Bl, size_t brow0, int ldb)
{
    uint32_t base = sb + 1024 + buf * STAGE_BYTES;
    #pragma unroll
    for (int ii = 0; ii < 6; ii++) {
        int i = tid + ii * NTHREADS;     // [0, 3072)
        int tno = i >> 10;               // 0=A, 1=Bh, 2=Bl (uniform per ii)
        int j = i & 1023;
        int r = j >> 3, v = j & 7;
        uint32_t dsw = sw128((uint32_t)(r * 128 + v * 16));
        if (tno == 0) {
            int ts = s_tok[r];
            size_t ar = (size_t)(a_is_pair ? (ts >> 1) : ts) * lda + k0 + v * 8;
            cp16(base + dsw, A + ar);
        } else if (tno == 1) {
            size_t wr = (brow0 + r) * (size_t)ldb + k0 + v * 8;
            cp16(base + 1 * TILE_BYTES + dsw, Bh + wr);
        } else {
            size_t wr = (brow0 + r) * (size_t)ldb + k0 + v * 8;
            cp16(base + 2 * TILE_BYTES + dsw, Bl + wr);
        }
    }
    CP_COMMIT();
}

// warp tile 32(M) x 32(N): per k16 step 6 ldsm4, 16 MMAs (2 terms of 8).
__device__ __forceinline__ void stage_compute(
    uint32_t sb, int buf, int wm, int wn, int lane, float acc[2][4][4])
{
    uint32_t base = sb + 1024 + buf * STAGE_BYTES;
    int lrow = lane & 15, lk = (lane >> 4) * 16;
    #pragma unroll
    for (int ks = 0; ks < 4; ks++) {
        int kb = ks * 32;
        uint32_t a[2][4], bh[2][4], bl[2][4];
        #pragma unroll
        for (int mt = 0; mt < 2; mt++) {
            uint32_t ro = (uint32_t)((wm * 32 + mt * 16 + lrow) * 128 + kb + lk);
            ldsm4(a[mt], base + sw128(ro));
        }
        #pragma unroll
        for (int np = 0; np < 2; np++) {
            uint32_t ro = (uint32_t)((wn * 32 + np * 16 + lrow) * 128 + kb + lk);
            ldsm4(bh[np], base + 1 * TILE_BYTES + sw128(ro));
            ldsm4(bl[np], base + 2 * TILE_BYTES + sw128(ro));
        }
        // term A*Bh
        #pragma unroll
        for (int mt = 0; mt < 2; mt++)
            #pragma unroll
            for (int np = 0; np < 2; np++) {
                mma16816(acc[mt][2*np],   a[mt], bh[np][0], bh[np][2]);
                mma16816(acc[mt][2*np+1], a[mt], bh[np][1], bh[np][3]);
            }
        // term A*Bl
        #pragma unroll
        for (int mt = 0; mt < 2; mt++)
            #pragma unroll
            for (int np = 0; np < 2; np++) {
                mma16816(acc[mt][2*np],   a[mt], bl[np][0], bl[np][2]);
                mma16816(acc[mt][2*np+1], a[mt], bl[np][1], bl[np][3]);
            }
    }
}

// ---------------- kernel 2: dense1 (fp16 2-term) + swiglu -> h fp16 ----------------
__global__ __launch_bounds__(NTHREADS, 1) void dense1_mma(const float* __restrict__ b1) {
    int e = blockIdx.z, rt = blockIdx.y, ct = blockIdx.x;
    int n = g_cnt[e];
    if (rt * TM >= n) return;

    extern __shared__ char smem[];
    int* s_tok = (int*)smem;
    int* s_val = (int*)(smem + 512);
    uint32_t sb = smem_u32(smem);
    int tid = threadIdx.x, lane = tid & 31, wid = tid >> 5;
    int wm = wid >> 2, wn = wid & 3;

    if (tid < TM) {
        int rg = rt * TM + tid;
        int cl = rg < n ? rg : n - 1;
        s_tok[tid] = g_entries[e][cl];
        s_val[tid] = rg < n;
    }
    __syncthreads();

    float acc[2][4][4];
    #pragma unroll
    for (int a = 0; a < 2; a++)
        #pragma unroll
        for (int b = 0; b < 4; b++)
            #pragma unroll
            for (int c = 0; c < 4; c++) acc[a][b][c] = 0.f;

    size_t brow0 = (size_t)e * TWO_F + (size_t)ct * TN;
    const int NS = D_DIM / KB;  // 16
    stage_load(sb, 0, 0, tid, s_tok, true, g_xf, D_DIM, g_w1h, g_w1l, brow0, D_DIM);
    stage_load(sb, 1, KB, tid, s_tok, true, g_xf, D_DIM, g_w1h, g_w1l, brow0, D_DIM);
    for (int s = 0; s < NS; s++) {
        if (s + 1 < NS) { CP_WAIT(1); } else { CP_WAIT(0); }
        __syncthreads();
        if (s + 2 < NS)
            stage_load(sb, (s + 2) % NSTAGE, (s + 2) * KB, tid, s_tok, true,
                       g_xf, D_DIM, g_w1h, g_w1l, brow0, D_DIM);
        stage_compute(sb, s % NSTAGE, wm, wn, lane, acc);
    }

    // epilogue: swiglu on (gate, value) adjacent even/odd cols
    #pragma unroll
    for (int mt = 0; mt < 2; mt++) {
        #pragma unroll
        for (int nt = 0; nt < 4; nt++) {
            int c = ct * TN + wn * 32 + nt * 8 + (lane & 3) * 2;
            float bg = b1[e * TWO_F + c];
            float bv = b1[e * TWO_F + c + 1];
            #pragma unroll
            for (int hrow = 0; hrow < 2; hrow++) {
                int r = wm * 32 + mt * 16 + (lane >> 2) + hrow * 8;
                if (!s_val[r]) continue;
                int ts = s_tok[r];
                float gpre = acc[mt][nt][hrow * 2 + 0] + bg;
                float vpre = acc[mt][nt][hrow * 2 + 1] + bv;
                float gg = fminf(gpre, 9.0f);
                float vv = fminf(fmaxf(vpre, -9.0f), 9.0f);
                float h = gg * (1.0f / (1.0f + expf(-1.702f * gg))) * (vv + 1.0f);
                g_hf[(size_t)ts * F_DIM + (c >> 1)] = __float2half_rn(h);
            }
        }
    }
}

// ---------------- kernel 3: dense2 (fp16 2-term) + bias + scale + atomic combine ----------------
__global__ __launch_bounds__(NTHREADS, 1) void dense2_mma(const float* __restrict__ b2,
                                                          float* __restrict__ out) {
    int e = blockIdx.z, rt = blockIdx.y, ct = blockIdx.x;
    int n = g_cnt[e];
    if (rt * TM >= n) return;

    extern __shared__ char smem[];
    int* s_tok = (int*)smem;
    int* s_val = (int*)(smem + 512);
    uint32_t sb = smem_u32(smem);
    int tid = threadIdx.x, lane = tid & 31, wid = tid >> 5;
    int wm = wid >> 2, wn = wid & 3;

    if (tid < TM) {
        int rg = rt * TM + tid;
        int cl = rg < n ? rg : n - 1;
        s_tok[tid] = g_entries[e][cl];
        s_val[tid] = rg < n;
    }
    __syncthreads();

    float acc[2][4][4];
    #pragma unroll
    for (int a = 0; a < 2; a++)
        #pragma unroll
        for (int b = 0; b < 4; b++)
            #pragma unroll
            for (int c = 0; c < 4; c++) acc[a][b][c] = 0.f;

    size_t brow0 = (size_t)e * D_DIM + (size_t)ct * TN;
    const int NS = F_DIM / KB;  // 32
    stage_load(sb, 0, 0, tid, s_tok, false, g_hf, F_DIM, g_w2h, g_w2l, brow0, F_DIM);
    stage_load(sb, 1, KB, tid, s_tok, false, g_hf, F_DIM, g_w2h, g_w2l, brow0, F_DIM);
    for (int s = 0; s < NS; s++) {
        if (s + 1 < NS) { CP_WAIT(1); } else { CP_WAIT(0); }
        __syncthreads();
        if (s + 2 < NS)
            stage_load(sb, (s + 2) % NSTAGE, (s + 2) * KB, tid, s_tok, false,
                       g_hf, F_DIM, g_w2h, g_w2l, brow0, F_DIM);
        stage_compute(sb, s % NSTAGE, wm, wn, lane, acc);
    }

    // per output element exactly 2 expert contributions; fp32 atomicAdd onto
    // zeroed out is commutative -> deterministic.
    #pragma unroll
    for (int mt = 0; mt < 2; mt++) {
        #pragma unroll
        for (int hrow = 0; hrow < 2; hrow++) {
            int r = wm * 32 + mt * 16 + (lane >> 2) + hrow * 8;
            if (!s_val[r]) continue;
            int ts = s_tok[r];
            float wgt = g_wts[ts >> 1][ts & 1];
            float* yrow = out + (size_t)(ts >> 1) * D_DIM;
            #pragma unroll
            for (int nt = 0; nt < 4; nt++) {
                int c = ct * TN + wn * 32 + nt * 8 + (lane & 3) * 2;
                atomicAdd(yrow + c,     (acc[mt][nt][hrow * 2 + 0] + b2[e * D_DIM + c]) * wgt);
                atomicAdd(yrow + c + 1, (acc[mt][nt][hrow * 2 + 1] + b2[e * D_DIM + c + 1]) * wgt);
            }
        }
    }
}

// ---------------- launch ----------------
extern "C" void kernel_launch(void* const* d_in, const int* in_sizes, int n_in,
                              void* d_out, int out_size) {
    const float* x  = (const float*)d_in[0];
    const float* gw = (const float*)d_in[1];
    const float* w1 = (const float*)d_in[2];
    const float* b1 = (const float*)d_in[3];
    const float* w2 = (const float*)d_in[4];
    const float* b2 = (const float*)d_in[5];
    float* out = (float*)d_out;

    cudaFuncSetAttribute(dense1_mma, cudaFuncAttributeMaxDynamicSharedMemorySize, SMEM_BYTES);
    cudaFuncSetAttribute(dense2_mma, cudaFuncAttributeMaxDynamicSharedMemorySize, SMEM_BYTES);

    zero_all_kernel<<<(T_TOKENS * D_DIM / 4 + 255) / 256, 256>>>((float4*)out);
    cvt_all_kernel<<<(NW14 + NW24 + NX4 + 255) / 256, 256>>>(
        (const float4*)x, (const float4*)w1, (const float4*)w2);
    gate_kernel<<<T_TOKENS / 4, 128>>>(x, gw);
    dense1_mma<<<dim3(TWO_F / TN, T_TOKENS / TM, E_EXP), NTHREADS, SMEM_BYTES>>>(b1);
    dense2_mma<<<dim3(D_DIM / TN, T_TOKENS / TM, E_EXP), NTHREADS, SMEM_BYTES>>>(b2, out);
}

// round 13
// speedup vs baseline: 1.4816x; 1.0002x over previous
#include <cuda_runtime.h>
#include <cuda_fp16.h>
#include <math.h>
#include <stdint.h>

#define T_TOKENS 4096
#define D_DIM    1024
#define E_EXP    8
#define F_DIM    2048
#define TWO_F    4096
#define NPAIR    (T_TOKENS * 2)

#define TM 128
#define TN 128
#define KB 64                     // K elements per stage (64 fp16 = 128B rows, SW128)
#define TILE_BYTES 16384          // 128 rows * 128 B
#define STAGE_BYTES (3 * TILE_BYTES)   // A, Bh, Bl
#define NSTAGE 3
#define SMEM_BYTES (1024 + NSTAGE * STAGE_BYTES)
#define NTHREADS 512

// ---------------- scratch (device globals; no allocs allowed) ----------------
__device__ int   g_cnt[E_EXP];
__device__ int   g_entries[E_EXP][T_TOKENS];
__device__ float g_wts[T_TOKENS][2];
__device__ __half g_xf[(size_t)T_TOKENS * D_DIM];
__device__ __half g_w1h[(size_t)E_EXP * TWO_F * D_DIM];
__device__ __half g_w1l[(size_t)E_EXP * TWO_F * D_DIM];
__device__ __half g_w2h[(size_t)E_EXP * D_DIM * F_DIM];
__device__ __half g_w2l[(size_t)E_EXP * D_DIM * F_DIM];
__device__ __half g_hf[(size_t)NPAIR * F_DIM];

// ---------------- helpers ----------------
__device__ __forceinline__ uint32_t smem_u32(const void* p) {
    uint32_t a;
    asm("{ .reg .u64 t; cvta.to.shared.u64 t, %1; cvt.u32.u64 %0, t; }" : "=r"(a) : "l"(p));
    return a;
}
__device__ __forceinline__ uint32_t sw128(uint32_t o) { return o ^ ((o >> 3) & 0x70); }

__device__ __forceinline__ void cp16(uint32_t dst, const void* src) {
    asm volatile("cp.async.cg.shared.global [%0], [%1], 16;" :: "r"(dst), "l"(src));
}
#define CP_COMMIT() asm volatile("cp.async.commit_group;" ::: "memory")
#define CP_WAIT(n)  asm volatile("cp.async.wait_group %0;" :: "n"(n) : "memory")

__device__ __forceinline__ void ldsm4(uint32_t* r, uint32_t addr) {
    asm volatile("ldmatrix.sync.aligned.m8n8.x4.shared.b16 {%0,%1,%2,%3}, [%4];"
        : "=r"(r[0]), "=r"(r[1]), "=r"(r[2]), "=r"(r[3]) : "r"(addr));
}
__device__ __forceinline__ void mma16816(float* d, const uint32_t* a, uint32_t b0, uint32_t b1) {
    asm volatile("mma.sync.aligned.m16n8k16.row.col.f32.f16.f16.f32 "
        "{%0,%1,%2,%3}, {%4,%5,%6,%7}, {%8,%9}, {%0,%1,%2,%3};"
        : "+f"(d[0]), "+f"(d[1]), "+f"(d[2]), "+f"(d[3])
        : "r"(a[0]), "r"(a[1]), "r"(a[2]), "r"(a[3]), "r"(b0), "r"(b1));
}

// ---------------- kernel 0: zero output + counters ----------------
__global__ void zero_all_kernel(float4* __restrict__ out) {
    int i = blockIdx.x * blockDim.x + threadIdx.x;
    if (i < T_TOKENS * D_DIM / 4) out[i] = make_float4(0.f, 0.f, 0.f, 0.f);
    if (blockIdx.x == 0 && threadIdx.x < E_EXP) g_cnt[threadIdx.x] = 0;
}

// ---------------- conversion ----------------
__device__ __forceinline__ void cvtw4(float4 f, uint2& H, uint2& L) {
    __half h0 = __float2half_rn(f.x), h1 = __float2half_rn(f.y);
    __half h2 = __float2half_rn(f.z), h3 = __float2half_rn(f.w);
    __half l0 = __float2half_rn(f.x - __half2float(h0));
    __half l1 = __float2half_rn(f.y - __half2float(h1));
    __half l2 = __float2half_rn(f.z - __half2float(h2));
    __half l3 = __float2half_rn(f.w - __half2float(h3));
    H.x = (uint32_t)__half_as_ushort(h0) | ((uint32_t)__half_as_ushort(h1) << 16);
    H.y = (uint32_t)__half_as_ushort(h2) | ((uint32_t)__half_as_ushort(h3) << 16);
    L.x = (uint32_t)__half_as_ushort(l0) | ((uint32_t)__half_as_ushort(l1) << 16);
    L.y = (uint32_t)__half_as_ushort(l2) | ((uint32_t)__half_as_ushort(l3) << 16);
}
#define NX4  (T_TOKENS * D_DIM / 4)
#define NW14 (E_EXP * TWO_F * D_DIM / 4)
#define NW24 (E_EXP * D_DIM * F_DIM / 4)
__global__ void cvt_all_kernel(const float4* __restrict__ x,
                               const float4* __restrict__ w1,
                               const float4* __restrict__ w2) {
    int i = blockIdx.x * blockDim.x + threadIdx.x;
    if (i < NW14) {
        uint2 H, L; cvtw4(w1[i], H, L);
        ((uint2*)g_w1h)[i] = H; ((uint2*)g_w1l)[i] = L;
    } else if (i < NW14 + NW24) {
        int j = i - NW14;
        uint2 H, L; cvtw4(w2[j], H, L);
        ((uint2*)g_w2h)[j] = H; ((uint2*)g_w2l)[j] = L;
    } else if (i < NW14 + NW24 + NX4) {
        int j = i - NW14 - NW24;
        float4 f = x[j];
        uint2 H;
        H.x = (uint32_t)__half_as_ushort(__float2half_rn(f.x)) |
              ((uint32_t)__half_as_ushort(__float2half_rn(f.y)) << 16);
        H.y = (uint32_t)__half_as_ushort(__float2half_rn(f.z)) |
              ((uint32_t)__half_as_ushort(__float2half_rn(f.w)) << 16);
        ((uint2*)g_xf)[j] = H;
    }
}

// ---------------- kernel 1: gate + top2 + routing ----------------
__global__ void gate_kernel(const float* __restrict__ x, const float* __restrict__ gw) {
    int warp = threadIdx.x >> 5;
    int lane = threadIdx.x & 31;
    int t = blockIdx.x * 4 + warp;
    float acc[8] = {0.f,0.f,0.f,0.f,0.f,0.f,0.f,0.f};
    const float* xr = x + (size_t)t * D_DIM;
    for (int d = lane; d < D_DIM; d += 32) {
        float xv = xr[d];
        const float* g = gw + d * 8;
        #pragma unroll
        for (int e = 0; e < 8; e++) acc[e] += xv * g[e];
    }
    #pragma unroll
    for (int off = 16; off > 0; off >>= 1)
        #pragma unroll
        for (int e = 0; e < 8; e++)
            acc[e] += __shfl_down_sync(0xffffffffu, acc[e], off);
    if (lane == 0) {
        int b0 = 0; float v0 = acc[0];
        #pragma unroll
        for (int e = 1; e < 8; e++) if (acc[e] > v0) { v0 = acc[e]; b0 = e; }
        int b1 = -1; float v1 = -3.4e38f;
        #pragma unroll
        for (int e = 0; e < 8; e++) if (e != b0 && acc[e] > v1) { v1 = acc[e]; b1 = e; }
        float w0 = 1.0f / (1.0f + expf(v1 - v0));
        g_wts[t][0] = w0;
        g_wts[t][1] = 1.0f - w0;
        int p0 = atomicAdd(&g_cnt[b0], 1);
        g_entries[b0][p0] = t * 2 + 0;
        int p1 = atomicAdd(&g_cnt[b1], 1);
        g_entries[b1][p1] = t * 2 + 1;
    }
}

// ---------------- shared GEMM machinery (512 threads, 16 warps, warp tile 32x32) ----------------
// smem: [0..512) s_tok, [512..1024) s_val, tiles @1024: stage{0..2} x {A, Bh, Bl}
__device__ __forceinline__ void stage_load(
    uint32_t sb, int buf, int k0, int tid,
    const int* s_tok, bool a_is_pair,
    const __half* A, int lda,
    const __half* Bh, const __half* Bl, size_t brow0, int ldb)
{
    uint32_t base = sb + 1024 + buf * STAGE_BYTES;
    #pragma unroll
    for (int ii = 0; ii < 6; ii++) {
        int i = tid + ii * NTHREADS;     // [0, 3072)
        int tno = i >> 10;               // 0=A, 1=Bh, 2=Bl (uniform per ii)
        int j = i & 1023;
        int r = j >> 3, v = j & 7;
        uint32_t dsw = sw128((uint32_t)(r * 128 + v * 16));
        if (tno == 0) {
            int ts = s_tok[r];
            size_t ar = (size_t)(a_is_pair ? (ts >> 1) : ts) * lda + k0 + v * 8;
            cp16(base + dsw, A + ar);
        } else if (tno == 1) {
            size_t wr = (brow0 + r) * (size_t)ldb + k0 + v * 8;
            cp16(base + 1 * TILE_BYTES + dsw, Bh + wr);
        } else {
            size_t wr = (brow0 + r) * (size_t)ldb + k0 + v * 8;
            cp16(base + 2 * TILE_BYTES + dsw, Bl + wr);
        }
    }
    CP_COMMIT();
}

// warp tile 32(M) x 32(N). Fragment-pipelined: a/bh double-buffered across k16
// steps (prefetch ks+1 before ks's MMAs); bl loaded at step top, consumed only
// after the 8-MMA A*Bh burst. Swizzle applied to the FULL offset each step
// (the xor mask shares bits [4:6] with the kb offset — cannot be hoisted).
__device__ __forceinline__ void stage_compute(
    uint32_t sb, int buf, int wm, int wn, int lane, float acc[2][4][4])
{
    uint32_t base = sb + 1024 + buf * STAGE_BYTES;
    uint32_t lrow = lane & 15, lk = (lane >> 4) * 16;
    uint32_t a[2][2][4], bh[2][2][4], bl[2][4];

    uint32_t ar0 = (uint32_t)(wm * 32 + 0  + lrow) * 128 + lk;
    uint32_t ar1 = (uint32_t)(wm * 32 + 16 + lrow) * 128 + lk;
    uint32_t br0 = (uint32_t)(wn * 32 + 0  + lrow) * 128 + lk;
    uint32_t br1 = (uint32_t)(wn * 32 + 16 + lrow) * 128 + lk;

    // preload ks=0 a, bh
    ldsm4(a[0][0], base + sw128(ar0));
    ldsm4(a[0][1], base + sw128(ar1));
    ldsm4(bh[0][0], base + 1 * TILE_BYTES + sw128(br0));
    ldsm4(bh[0][1], base + 1 * TILE_BYTES + sw128(br1));

    #pragma unroll
    for (int ks = 0; ks < 4; ks++) {
        int cur = ks & 1, nxt = cur ^ 1;
        uint32_t kb = ks * 32;
        // bl for current step
        ldsm4(bl[0], base + 2 * TILE_BYTES + sw128(br0 + kb));
        ldsm4(bl[1], base + 2 * TILE_BYTES + sw128(br1 + kb));
        // prefetch a, bh for next step
        if (ks < 3) {
            uint32_t kb2 = kb + 32;
            ldsm4(a[nxt][0], base + sw128(ar0 + kb2));
            ldsm4(a[nxt][1], base + sw128(ar1 + kb2));
            ldsm4(bh[nxt][0], base + 1 * TILE_BYTES + sw128(br0 + kb2));
            ldsm4(bh[nxt][1], base + 1 * TILE_BYTES + sw128(br1 + kb2));
        }
        // term A*Bh (fragments loaded one step ago)
        #pragma unroll
        for (int mt = 0; mt < 2; mt++)
            #pragma unroll
            for (int np = 0; np < 2; np++) {
                mma16816(acc[mt][2*np],   a[cur][mt], bh[cur][np][0], bh[cur][np][2]);
                mma16816(acc[mt][2*np+1], a[cur][mt], bh[cur][np][1], bh[cur][np][3]);
            }
        // term A*Bl (bl loaded 8 MMAs ago)
        #pragma unroll
        for (int mt = 0; mt < 2; mt++)
            #pragma unroll
            for (int np = 0; np < 2; np++) {
                mma16816(acc[mt][2*np],   a[cur][mt], bl[np][0], bl[np][2]);
                mma16816(acc[mt][2*np+1], a[cur][mt], bl[np][1], bl[np][3]);
            }
    }
}

// ---------------- kernel 2: dense1 (fp16 2-term) + swiglu -> h fp16 ----------------
__global__ __launch_bounds__(NTHREADS, 1) void dense1_mma(const float* __restrict__ b1) {
    int e = blockIdx.z, rt = blockIdx.y, ct = blockIdx.x;
    int n = g_cnt[e];
    if (rt * TM >= n) return;

    extern __shared__ char smem[];
    int* s_tok = (int*)smem;
    int* s_val = (int*)(smem + 512);
    uint32_t sb = smem_u32(smem);
    int tid = threadIdx.x, lane = tid & 31, wid = tid >> 5;
    int wm = wid >> 2, wn = wid & 3;

    if (tid < TM) {
        int rg = rt * TM + tid;
        int cl = rg < n ? rg : n - 1;
        s_tok[tid] = g_entries[e][cl];
        s_val[tid] = rg < n;
    }
    __syncthreads();

    float acc[2][4][4];
    #pragma unroll
    for (int a = 0; a < 2; a++)
        #pragma unroll
        for (int b = 0; b < 4; b++)
            #pragma unroll
            for (int c = 0; c < 4; c++) acc[a][b][c] = 0.f;

    size_t brow0 = (size_t)e * TWO_F + (size_t)ct * TN;
    const int NS = D_DIM / KB;  // 16
    stage_load(sb, 0, 0, tid, s_tok, true, g_xf, D_DIM, g_w1h, g_w1l, brow0, D_DIM);
    stage_load(sb, 1, KB, tid, s_tok, true, g_xf, D_DIM, g_w1h, g_w1l, brow0, D_DIM);
    for (int s = 0; s < NS; s++) {
        if (s + 1 < NS) { CP_WAIT(1); } else { CP_WAIT(0); }
        __syncthreads();
        if (s + 2 < NS)
            stage_load(sb, (s + 2) % NSTAGE, (s + 2) * KB, tid, s_tok, true,
                       g_xf, D_DIM, g_w1h, g_w1l, brow0, D_DIM);
        stage_compute(sb, s % NSTAGE, wm, wn, lane, acc);
    }

    // epilogue: swiglu on (gate, value) adjacent even/odd cols
    #pragma unroll
    for (int mt = 0; mt < 2; mt++) {
        #pragma unroll
        for (int nt = 0; nt < 4; nt++) {
            int c = ct * TN + wn * 32 + nt * 8 + (lane & 3) * 2;
            float bg = b1[e * TWO_F + c];
            float bv = b1[e * TWO_F + c + 1];
            #pragma unroll
            for (int hrow = 0; hrow < 2; hrow++) {
                int r = wm * 32 + mt * 16 + (lane >> 2) + hrow * 8;
                if (!s_val[r]) continue;
                int ts = s_tok[r];
                float gpre = acc[mt][nt][hrow * 2 + 0] + bg;
                float vpre = acc[mt][nt][hrow * 2 + 1] + bv;
                float gg = fminf(gpre, 9.0f);
                float vv = fminf(fmaxf(vpre, -9.0f), 9.0f);
                float h = gg * (1.0f / (1.0f + expf(-1.702f * gg))) * (vv + 1.0f);
                g_hf[(size_t)ts * F_DIM + (c >> 1)] = __float2half_rn(h);
            }
        }
    }
}

// ---------------- kernel 3: dense2 (fp16 2-term) + bias + scale + atomic combine ----------------
__global__ __launch_bounds__(NTHREADS, 1) void dense2_mma(const float* __restrict__ b2,
                                                          float* __restrict__ out) {
    int e = blockIdx.z, rt = blockIdx.y, ct = blockIdx.x;
    int n = g_cnt[e];
    if (rt * TM >= n) return;

    extern __shared__ char smem[];
    int* s_tok = (int*)smem;
    int* s_val = (int*)(smem + 512);
    uint32_t sb = smem_u32(smem);
    int tid = threadIdx.x, lane = tid & 31, wid = tid >> 5;
    int wm = wid >> 2, wn = wid & 3;

    if (tid < TM) {
        int rg = rt * TM + tid;
        int cl = rg < n ? rg : n - 1;
        s_tok[tid] = g_entries[e][cl];
        s_val[tid] = rg < n;
    }
    __syncthreads();

    float acc[2][4][4];
    #pragma unroll
    for (int a = 0; a < 2; a++)
        #pragma unroll
        for (int b = 0; b < 4; b++)
            #pragma unroll
            for (int c = 0; c < 4; c++) acc[a][b][c] = 0.f;

    size_t brow0 = (size_t)e * D_DIM + (size_t)ct * TN;
    const int NS = F_DIM / KB;  // 32
    stage_load(sb, 0, 0, tid, s_tok, false, g_hf, F_DIM, g_w2h, g_w2l, brow0, F_DIM);
    stage_load(sb, 1, KB, tid, s_tok, false, g_hf, F_DIM, g_w2h, g_w2l, brow0, F_DIM);
    for (int s = 0; s < NS; s++) {
        if (s + 1 < NS) { CP_WAIT(1); } else { CP_WAIT(0); }
        __syncthreads();
        if (s + 2 < NS)
            stage_load(sb, (s + 2) % NSTAGE, (s + 2) * KB, tid, s_tok, false,
                       g_hf, F_DIM, g_w2h, g_w2l, brow0, F_DIM);
        stage_compute(sb, s % NSTAGE, wm, wn, lane, acc);
    }

    // per output element exactly 2 expert contributions; fp32 atomicAdd onto
    // zeroed out is commutative -> deterministic.
    #pragma unroll
    for (int mt = 0; mt < 2; mt++) {
        #pragma unroll
        for (int hrow = 0; hrow < 2; hrow++) {
            int r = wm * 32 + mt * 16 + (lane >> 2) + hrow * 8;
            if (!s_val[r]) continue;
            int ts = s_tok[r];
            float wgt = g_wts[ts >> 1][ts & 1];
            float* yrow = out + (size_t)(ts >> 1) * D_DIM;
            #pragma unroll
            for (int nt = 0; nt < 4; nt++) {
                int c = ct * TN + wn * 32 + nt * 8 + (lane & 3) * 2;
                atomicAdd(yrow + c,     (acc[mt][nt][hrow * 2 + 0] + b2[e * D_DIM + c]) * wgt);
                atomicAdd(yrow + c + 1, (acc[mt][nt][hrow * 2 + 1] + b2[e * D_DIM + c + 1]) * wgt);
            }
        }
    }
}

// ---------------- launch ----------------
extern "C" void kernel_launch(void* const* d_in, const int* in_sizes, int n_in,
                              void* d_out, int out_size) {
    const float* x  = (const float*)d_in[0];
    const float* gw = (const float*)d_in[1];
    const float* w1 = (const float*)d_in[2];
    const float* b1 = (const float*)d_in[3];
    const float* w2 = (const float*)d_in[4];
    const float* b2 = (const float*)d_in[5];
    float* out = (float*)d_out;

    cudaFuncSetAttribute(dense1_mma, cudaFuncAttributeMaxDynamicSharedMemorySize, SMEM_BYTES);
    cudaFuncSetAttribute(dense2_mma, cudaFuncAttributeMaxDynamicSharedMemorySize, SMEM_BYTES);

    zero_all_kernel<<<(T_TOKENS * D_DIM / 4 + 255) / 256, 256>>>((float4*)out);
    cvt_all_kernel<<<(NW14 + NW24 + NX4 + 255) / 256, 256>>>(
        (const float4*)x, (const float4*)w1, (const float4*)w2);
    gate_kernel<<<T_TOKENS / 4, 128>>>(x, gw);
    dense1_mma<<<dim3(TWO_F / TN, T_TOKENS / TM, E_EXP), NTHREADS, SMEM_BYTES>>>(b1);
    dense2_mma<<<dim3(D_DIM / TN, T_TOKENS / TM, E_EXP), NTHREADS, SMEM_BYTES>>>(b2, out);
}

// round 14
// speedup vs baseline: 1.6109x; 1.0873x over previous
#include <cuda_runtime.h>
#include <cuda_fp16.h>
#include <math.h>
#include <stdint.h>

#define T_TOKENS 4096
#define D_DIM    1024
#define E_EXP    8
#define F_DIM    2048
#define TWO_F    4096
#define NPAIR    (T_TOKENS * 2)

#define TM 128
#define TN 64
#define KB 64                     // K elements per stage (64 fp16 = 128B rows, SW128)
#define A_TILE_BYTES 16384        // 128 rows * 128 B
#define B_TILE_BYTES 8192         // 64 rows * 128 B
#define STAGE_BYTES (A_TILE_BYTES + 2 * B_TILE_BYTES)   // A, Bh, Bl = 32 KB
#define NSTAGE 3
#define SMEM_BYTES (1024 + NSTAGE * STAGE_BYTES)        // 97 KB -> 2 CTAs/SM
#define NTHREADS 256

// ---------------- scratch (device globals; no allocs allowed) ----------------
__device__ int   g_cnt[E_EXP];
__device__ int   g_entries[E_EXP][T_TOKENS];
__device__ float g_wts[T_TOKENS][2];
__device__ __half g_xf[(size_t)T_TOKENS * D_DIM];
__device__ __half g_w1h[(size_t)E_EXP * TWO_F * D_DIM];
__device__ __half g_w1l[(size_t)E_EXP * TWO_F * D_DIM];
__device__ __half g_w2h[(size_t)E_EXP * D_DIM * F_DIM];
__device__ __half g_w2l[(size_t)E_EXP * D_DIM * F_DIM];
__device__ __half g_hf[(size_t)NPAIR * F_DIM];

// ---------------- helpers ----------------
__device__ __forceinline__ uint32_t smem_u32(const void* p) {
    uint32_t a;
    asm("{ .reg .u64 t; cvta.to.shared.u64 t, %1; cvt.u32.u64 %0, t; }" : "=r"(a) : "l"(p));
    return a;
}
__device__ __forceinline__ uint32_t sw128(uint32_t o) { return o ^ ((o >> 3) & 0x70); }

__device__ __forceinline__ void cp16(uint32_t dst, const void* src) {
    asm volatile("cp.async.cg.shared.global [%0], [%1], 16;" :: "r"(dst), "l"(src));
}
#define CP_COMMIT() asm volatile("cp.async.commit_group;" ::: "memory")
#define CP_WAIT(n)  asm volatile("cp.async.wait_group %0;" :: "n"(n) : "memory")

__device__ __forceinline__ void ldsm4(uint32_t* r, uint32_t addr) {
    asm volatile("ldmatrix.sync.aligned.m8n8.x4.shared.b16 {%0,%1,%2,%3}, [%4];"
        : "=r"(r[0]), "=r"(r[1]), "=r"(r[2]), "=r"(r[3]) : "r"(addr));
}
__device__ __forceinline__ void mma16816(float* d, const uint32_t* a, uint32_t b0, uint32_t b1) {
    asm volatile("mma.sync.aligned.m16n8k16.row.col.f32.f16.f16.f32 "
        "{%0,%1,%2,%3}, {%4,%5,%6,%7}, {%8,%9}, {%0,%1,%2,%3};"
        : "+f"(d[0]), "+f"(d[1]), "+f"(d[2]), "+f"(d[3])
        : "r"(a[0]), "r"(a[1]), "r"(a[2]), "r"(a[3]), "r"(b0), "r"(b1));
}

// ---------------- kernel 0: zero output + counters ----------------
__global__ void zero_all_kernel(float4* __restrict__ out) {
    int i = blockIdx.x * blockDim.x + threadIdx.x;
    if (i < T_TOKENS * D_DIM / 4) out[i] = make_float4(0.f, 0.f, 0.f, 0.f);
    if (blockIdx.x == 0 && threadIdx.x < E_EXP) g_cnt[threadIdx.x] = 0;
}

// ---------------- conversion ----------------
__device__ __forceinline__ void cvtw4(float4 f, uint2& H, uint2& L) {
    __half h0 = __float2half_rn(f.x), h1 = __float2half_rn(f.y);
    __half h2 = __float2half_rn(f.z), h3 = __float2half_rn(f.w);
    __half l0 = __float2half_rn(f.x - __half2float(h0));
    __half l1 = __float2half_rn(f.y - __half2float(h1));
    __half l2 = __float2half_rn(f.z - __half2float(h2));
    __half l3 = __float2half_rn(f.w - __half2float(h3));
    H.x = (uint32_t)__half_as_ushort(h0) | ((uint32_t)__half_as_ushort(h1) << 16);
    H.y = (uint32_t)__half_as_ushort(h2) | ((uint32_t)__half_as_ushort(h3) << 16);
    L.x = (uint32_t)__half_as_ushort(l0) | ((uint32_t)__half_as_ushort(l1) << 16);
    L.y = (uint32_t)__half_as_ushort(l2) | ((uint32_t)__half_as_ushort(l3) << 16);
}
#define NX4  (T_TOKENS * D_DIM / 4)
#define NW14 (E_EXP * TWO_F * D_DIM / 4)
#define NW24 (E_EXP * D_DIM * F_DIM / 4)
__global__ void cvt_all_kernel(const float4* __restrict__ x,
                               const float4* __restrict__ w1,
                               const float4* __restrict__ w2) {
    int i = blockIdx.x * blockDim.x + threadIdx.x;
    if (i < NW14) {
        uint2 H, L; cvtw4(w1[i], H, L);
        ((uint2*)g_w1h)[i] = H; ((uint2*)g_w1l)[i] = L;
    } else if (i < NW14 + NW24) {
        int j = i - NW14;
        uint2 H, L; cvtw4(w2[j], H, L);
        ((uint2*)g_w2h)[j] = H; ((uint2*)g_w2l)[j] = L;
    } else if (i < NW14 + NW24 + NX4) {
        int j = i - NW14 - NW24;
        float4 f = x[j];
        uint2 H;
        H.x = (uint32_t)__half_as_ushort(__float2half_rn(f.x)) |
              ((uint32_t)__half_as_ushort(__float2half_rn(f.y)) << 16);
        H.y = (uint32_t)__half_as_ushort(__float2half_rn(f.z)) |
              ((uint32_t)__half_as_ushort(__float2half_rn(f.w)) << 16);
        ((uint2*)g_xf)[j] = H;
    }
}

// ---------------- kernel 1: gate + top2 + routing ----------------
__global__ void gate_kernel(const float* __restrict__ x, const float* __restrict__ gw) {
    int warp = threadIdx.x >> 5;
    int lane = threadIdx.x & 31;
    int t = blockIdx.x * 4 + warp;
    float acc[8] = {0.f,0.f,0.f,0.f,0.f,0.f,0.f,0.f};
    const float* xr = x + (size_t)t * D_DIM;
    for (int d = lane; d < D_DIM; d += 32) {
        float xv = xr[d];
        const float* g = gw + d * 8;
        #pragma unroll
        for (int e = 0; e < 8; e++) acc[e] += xv * g[e];
    }
    #pragma unroll
    for (int off = 16; off > 0; off >>= 1)
        #pragma unroll
        for (int e = 0; e < 8; e++)
            acc[e] += __shfl_down_sync(0xffffffffu, acc[e], off);
    if (lane == 0) {
        int b0 = 0; float v0 = acc[0];
        #pragma unroll
        for (int e = 1; e < 8; e++) if (acc[e] > v0) { v0 = acc[e]; b0 = e; }
        int b1 = -1; float v1 = -3.4e38f;
        #pragma unroll
        for (int e = 0; e < 8; e++) if (e != b0 && acc[e] > v1) { v1 = acc[e]; b1 = e; }
        float w0 = 1.0f / (1.0f + expf(v1 - v0));
        g_wts[t][0] = w0;
        g_wts[t][1] = 1.0f - w0;
        int p0 = atomicAdd(&g_cnt[b0], 1);
        g_entries[b0][p0] = t * 2 + 0;
        int p1 = atomicAdd(&g_cnt[b1], 1);
        g_entries[b1][p1] = t * 2 + 1;
    }
}

// ---------------- shared GEMM machinery (256 threads, 8 warps, warp tile 32x32) ----------------
// CTA tile 128(M) x 64(N); warp grid 4(M) x 2(N). 2 CTAs/SM.
// smem: [0..512) s_tok, [512..1024) s_val, tiles @1024: stage{0..2} x {A, Bh, Bl}
__device__ __forceinline__ void stage_load(
    uint32_t sb, int buf, int k0, int tid,
    const int* s_tok, bool a_is_pair,
    const __half* A, int lda,
    const __half* Bh, const __half* Bl, size_t brow0, int ldb)
{
    uint32_t base = sb + 1024 + buf * STAGE_BYTES;
    #pragma unroll
    for (int ii = 0; ii < 8; ii++) {
        int i = tid + ii * NTHREADS;     // [0, 2048)
        if (i < 1024) {                  // A: 128 rows x 8 vec16
            int r = i >> 3, v = i & 7;
            uint32_t dsw = sw128((uint32_t)(r * 128 + v * 16));
            int ts = s_tok[r];
            size_t ar = (size_t)(a_is_pair ? (ts >> 1) : ts) * lda + k0 + v * 8;
            cp16(base + dsw, A + ar);
        } else if (i < 1536) {           // Bh: 64 rows x 8 vec16
            int j = i - 1024;
            int r = j >> 3, v = j & 7;
            uint32_t dsw = sw128((uint32_t)(r * 128 + v * 16));
            size_t wr = (brow0 + r) * (size_t)ldb + k0 + v * 8;
            cp16(base + A_TILE_BYTES + dsw, Bh + wr);
        } else {                         // Bl
            int j = i - 1536;
            int r = j >> 3, v = j & 7;
            uint32_t dsw = sw128((uint32_t)(r * 128 + v * 16));
            size_t wr = (brow0 + r) * (size_t)ldb + k0 + v * 8;
            cp16(base + A_TILE_BYTES + B_TILE_BYTES + dsw, Bl + wr);
        }
    }
    CP_COMMIT();
}

// warp tile 32(M) x 32(N). Fragment-pipelined: a/bh double-buffered across k16
// steps; bl loaded at step top, consumed after the 8-MMA A*Bh burst.
__device__ __forceinline__ void stage_compute(
    uint32_t sb, int buf, int wm, int wn, int lane, float acc[2][4][4])
{
    uint32_t base = sb + 1024 + buf * STAGE_BYTES;
    uint32_t lrow = lane & 15, lk = (lane >> 4) * 16;
    uint32_t a[2][2][4], bh[2][2][4], bl[2][4];

    uint32_t ar0 = (uint32_t)(wm * 32 + 0  + lrow) * 128 + lk;
    uint32_t ar1 = (uint32_t)(wm * 32 + 16 + lrow) * 128 + lk;
    uint32_t br0 = (uint32_t)(wn * 32 + 0  + lrow) * 128 + lk;
    uint32_t br1 = (uint32_t)(wn * 32 + 16 + lrow) * 128 + lk;

    ldsm4(a[0][0], base + sw128(ar0));
    ldsm4(a[0][1], base + sw128(ar1));
    ldsm4(bh[0][0], base + A_TILE_BYTES + sw128(br0));
    ldsm4(bh[0][1], base + A_TILE_BYTES + sw128(br1));

    #pragma unroll
    for (int ks = 0; ks < 4; ks++) {
        int cur = ks & 1, nxt = cur ^ 1;
        uint32_t kb = ks * 32;
        ldsm4(bl[0], base + A_TILE_BYTES + B_TILE_BYTES + sw128(br0 + kb));
        ldsm4(bl[1], base + A_TILE_BYTES + B_TILE_BYTES + sw128(br1 + kb));
        if (ks < 3) {
            uint32_t kb2 = kb + 32;
            ldsm4(a[nxt][0], base + sw128(ar0 + kb2));
            ldsm4(a[nxt][1], base + sw128(ar1 + kb2));
            ldsm4(bh[nxt][0], base + A_TILE_BYTES + sw128(br0 + kb2));
            ldsm4(bh[nxt][1], base + A_TILE_BYTES + sw128(br1 + kb2));
        }
        // term A*Bh
        #pragma unroll
        for (int mt = 0; mt < 2; mt++)
            #pragma unroll
            for (int np = 0; np < 2; np++) {
                mma16816(acc[mt][2*np],   a[cur][mt], bh[cur][np][0], bh[cur][np][2]);
                mma16816(acc[mt][2*np+1], a[cur][mt], bh[cur][np][1], bh[cur][np][3]);
            }
        // term A*Bl
        #pragma unroll
        for (int mt = 0; mt < 2; mt++)
            #pragma unroll
            for (int np = 0; np < 2; np++) {
                mma16816(acc[mt][2*np],   a[cur][mt], bl[np][0], bl[np][2]);
                mma16816(acc[mt][2*np+1], a[cur][mt], bl[np][1], bl[np][3]);
            }
    }
}

// ---------------- kernel 2: dense1 (fp16 2-term) + swiglu -> h fp16 ----------------
__global__ __launch_bounds__(NTHREADS, 2) void dense1_mma(const float* __restrict__ b1) {
    int e = blockIdx.z, rt = blockIdx.y, ct = blockIdx.x;
    int n = g_cnt[e];
    if (rt * TM >= n) return;

    extern __shared__ char smem[];
    int* s_tok = (int*)smem;
    int* s_val = (int*)(smem + 512);
    uint32_t sb = smem_u32(smem);
    int tid = threadIdx.x, lane = tid & 31, wid = tid >> 5;
    int wm = wid >> 1, wn = wid & 1;

    if (tid < TM) {
        int rg = rt * TM + tid;
        int cl = rg < n ? rg : n - 1;
        s_tok[tid] = g_entries[e][cl];
        s_val[tid] = rg < n;
    }
    __syncthreads();

    float acc[2][4][4];
    #pragma unroll
    for (int a = 0; a < 2; a++)
        #pragma unroll
        for (int b = 0; b < 4; b++)
            #pragma unroll
            for (int c = 0; c < 4; c++) acc[a][b][c] = 0.f;

    size_t brow0 = (size_t)e * TWO_F + (size_t)ct * TN;
    const int NS = D_DIM / KB;  // 16
    stage_load(sb, 0, 0, tid, s_tok, true, g_xf, D_DIM, g_w1h, g_w1l, brow0, D_DIM);
    stage_load(sb, 1, KB, tid, s_tok, true, g_xf, D_DIM, g_w1h, g_w1l, brow0, D_DIM);
    for (int s = 0; s < NS; s++) {
        if (s + 1 < NS) { CP_WAIT(1); } else { CP_WAIT(0); }
        __syncthreads();
        if (s + 2 < NS)
            stage_load(sb, (s + 2) % NSTAGE, (s + 2) * KB, tid, s_tok, true,
                       g_xf, D_DIM, g_w1h, g_w1l, brow0, D_DIM);
        stage_compute(sb, s % NSTAGE, wm, wn, lane, acc);
    }

    // epilogue: swiglu on (gate, value) adjacent even/odd cols
    #pragma unroll
    for (int mt = 0; mt < 2; mt++) {
        #pragma unroll
        for (int nt = 0; nt < 4; nt++) {
            int c = ct * TN + wn * 32 + nt * 8 + (lane & 3) * 2;
            float bg = b1[e * TWO_F + c];
            float bv = b1[e * TWO_F + c + 1];
            #pragma unroll
            for (int hrow = 0; hrow < 2; hrow++) {
                int r = wm * 32 + mt * 16 + (lane >> 2) + hrow * 8;
                if (!s_val[r]) continue;
                int ts = s_tok[r];
                float gpre = acc[mt][nt][hrow * 2 + 0] + bg;
                float vpre = acc[mt][nt][hrow * 2 + 1] + bv;
                float gg = fminf(gpre, 9.0f);
                float vv = fminf(fmaxf(vpre, -9.0f), 9.0f);
                float h = gg * (1.0f / (1.0f + expf(-1.702f * gg))) * (vv + 1.0f);
                g_hf[(size_t)ts * F_DIM + (c >> 1)] = __float2half_rn(h);
            }
        }
    }
}

// ---------------- kernel 3: dense2 (fp16 2-term) + bias + scale + atomic combine ----------------
__global__ __launch_bounds__(NTHREADS, 2) void dense2_mma(const float* __restrict__ b2,
                                                          float* __restrict__ out) {
    int e = blockIdx.z, rt = blockIdx.y, ct = blockIdx.x;
    int n = g_cnt[e];
    if (rt * TM >= n) return;

    extern __shared__ char smem[];
    int* s_tok = (int*)smem;
    int* s_val = (int*)(smem + 512);
    uint32_t sb = smem_u32(smem);
    int tid = threadIdx.x, lane = tid & 31, wid = tid >> 5;
    int wm = wid >> 1, wn = wid & 1;

    if (tid < TM) {
        int rg = rt * TM + tid;
        int cl = rg < n ? rg : n - 1;
        s_tok[tid] = g_entries[e][cl];
        s_val[tid] = rg < n;
    }
    __syncthreads();

    float acc[2][4][4];
    #pragma unroll
    for (int a = 0; a < 2; a++)
        #pragma unroll
        for (int b = 0; b < 4; b++)
            #pragma unroll
            for (int c = 0; c < 4; c++) acc[a][b][c] = 0.f;

    size_t brow0 = (size_t)e * D_DIM + (size_t)ct * TN;
    const int NS = F_DIM / KB;  // 32
    stage_load(sb, 0, 0, tid, s_tok, false, g_hf, F_DIM, g_w2h, g_w2l, brow0, F_DIM);
    stage_load(sb, 1, KB, tid, s_tok, false, g_hf, F_DIM, g_w2h, g_w2l, brow0, F_DIM);
    for (int s = 0; s < NS; s++) {
        if (s + 1 < NS) { CP_WAIT(1); } else { CP_WAIT(0); }
        __syncthreads();
        if (s + 2 < NS)
            stage_load(sb, (s + 2) % NSTAGE, (s + 2) * KB, tid, s_tok, false,
                       g_hf, F_DIM, g_w2h, g_w2l, brow0, F_DIM);
        stage_compute(sb, s % NSTAGE, wm, wn, lane, acc);
    }

    // per output element exactly 2 expert contributions; fp32 atomicAdd onto
    // zeroed out is commutative -> deterministic.
    #pragma unroll
    for (int mt = 0; mt < 2; mt++) {
        #pragma unroll
        for (int hrow = 0; hrow < 2; hrow++) {
            int r = wm * 32 + mt * 16 + (lane >> 2) + hrow * 8;
            if (!s_val[r]) continue;
            int ts = s_tok[r];
            float wgt = g_wts[ts >> 1][ts & 1];
            float* yrow = out + (size_t)(ts >> 1) * D_DIM;
            #pragma unroll
            for (int nt = 0; nt < 4; nt++) {
                int c = ct * TN + wn * 32 + nt * 8 + (lane & 3) * 2;
                atomicAdd(yrow + c,     (acc[mt][nt][hrow * 2 + 0] + b2[e * D_DIM + c]) * wgt);
                atomicAdd(yrow + c + 1, (acc[mt][nt][hrow * 2 + 1] + b2[e * D_DIM + c + 1]) * wgt);
            }
        }
    }
}

// ---------------- launch ----------------
extern "C" void kernel_launch(void* const* d_in, const int* in_sizes, int n_in,
                              void* d_out, int out_size) {
    const float* x  = (const float*)d_in[0];
    const float* gw = (const float*)d_in[1];
    const float* w1 = (const float*)d_in[2];
    const float* b1 = (const float*)d_in[3];
    const float* w2 = (const float*)d_in[4];
    const float* b2 = (const float*)d_in[5];
    float* out = (float*)d_out;

    cudaFuncSetAttribute(dense1_mma, cudaFuncAttributeMaxDynamicSharedMemorySize, SMEM_BYTES);
    cudaFuncSetAttribute(dense2_mma, cudaFuncAttributeMaxDynamicSharedMemorySize, SMEM_BYTES);

    zero_all_kernel<<<(T_TOKENS * D_DIM / 4 + 255) / 256, 256>>>((float4*)out);
    cvt_all_kernel<<<(NW14 + NW24 + NX4 + 255) / 256, 256>>>(
        (const float4*)x, (const float4*)w1, (const float4*)w2);
    gate_kernel<<<T_TOKENS / 4, 128>>>(x, gw);
    dense1_mma<<<dim3(TWO_F / TN, T_TOKENS / TM, E_EXP), NTHREADS, SMEM_BYTES>>>(b1);
    dense2_mma<<<dim3(D_DIM / TN, T_TOKENS / TM, E_EXP), NTHREADS, SMEM_BYTES>>>(b2, out);
}

// round 15
// speedup vs baseline: 2.6450x; 1.6420x over previous
#include <cuda_runtime.h>
#include <cuda_fp16.h>
#include <math.h>
#include <stdint.h>

#define T_TOKENS 4096
#define D_DIM    1024
#define E_EXP    8
#define F_DIM    2048
#define TWO_F    4096
#define NPAIR    (T_TOKENS * 2)

#define TM 128
#define TN 128
#define KB 64                     // K elements per stage (64 fp16 = 128B rows, SW128)
#define A_TILE_BYTES 16384        // 128 rows * 128 B
#define B_TILE_BYTES 16384        // 128 rows * 128 B
#define STAGE_BYTES (A_TILE_BYTES + B_TILE_BYTES)       // 32 KB
#define NSTAGE 3
#define SMEM_BYTES (1024 + NSTAGE * STAGE_BYTES)        // 97 KB -> 2 CTAs/SM
#define NTHREADS 256

// ---------------- scratch (device globals; no allocs allowed) ----------------
__device__ int   g_cnt[E_EXP];
__device__ int   g_entries[E_EXP][T_TOKENS];
__device__ float g_wts[T_TOKENS][2];
__device__ __half g_xf[(size_t)T_TOKENS * D_DIM];
__device__ __half g_w1h[(size_t)E_EXP * TWO_F * D_DIM];
__device__ __half g_w2h[(size_t)E_EXP * D_DIM * F_DIM];
__device__ __half g_hf[(size_t)NPAIR * F_DIM];

// ---------------- helpers ----------------
__device__ __forceinline__ uint32_t smem_u32(const void* p) {
    uint32_t a;
    asm("{ .reg .u64 t; cvta.to.shared.u64 t, %1; cvt.u32.u64 %0, t; }" : "=r"(a) : "l"(p));
    return a;
}
__device__ __forceinline__ uint32_t sw128(uint32_t o) { return o ^ ((o >> 3) & 0x70); }

__device__ __forceinline__ void cp16(uint32_t dst, const void* src) {
    asm volatile("cp.async.cg.shared.global [%0], [%1], 16;" :: "r"(dst), "l"(src));
}
#define CP_COMMIT() asm volatile("cp.async.commit_group;" ::: "memory")
#define CP_WAIT(n)  asm volatile("cp.async.wait_group %0;" :: "n"(n) : "memory")

__device__ __forceinline__ void ldsm4(uint32_t* r, uint32_t addr) {
    asm volatile("ldmatrix.sync.aligned.m8n8.x4.shared.b16 {%0,%1,%2,%3}, [%4];"
        : "=r"(r[0]), "=r"(r[1]), "=r"(r[2]), "=r"(r[3]) : "r"(addr));
}
__device__ __forceinline__ void mma16816(float* d, const uint32_t* a, uint32_t b0, uint32_t b1) {
    asm volatile("mma.sync.aligned.m16n8k16.row.col.f32.f16.f16.f32 "
        "{%0,%1,%2,%3}, {%4,%5,%6,%7}, {%8,%9}, {%0,%1,%2,%3};"
        : "+f"(d[0]), "+f"(d[1]), "+f"(d[2]), "+f"(d[3])
        : "r"(a[0]), "r"(a[1]), "r"(a[2]), "r"(a[3]), "r"(b0), "r"(b1));
}

// ---------------- kernel 0: zero output + counters ----------------
__global__ void zero_all_kernel(float4* __restrict__ out) {
    int i = blockIdx.x * blockDim.x + threadIdx.x;
    if (i < T_TOKENS * D_DIM / 4) out[i] = make_float4(0.f, 0.f, 0.f, 0.f);
    if (blockIdx.x == 0 && threadIdx.x < E_EXP) g_cnt[threadIdx.x] = 0;
}

// ---------------- conversion: fp32 -> fp16 (single term) ----------------
__device__ __forceinline__ uint2 cvth4(float4 f) {
    uint2 H;
    H.x = (uint32_t)__half_as_ushort(__float2half_rn(f.x)) |
          ((uint32_t)__half_as_ushort(__float2half_rn(f.y)) << 16);
    H.y = (uint32_t)__half_as_ushort(__float2half_rn(f.z)) |
          ((uint32_t)__half_as_ushort(__float2half_rn(f.w)) << 16);
    return H;
}
#define NX4  (T_TOKENS * D_DIM / 4)
#define NW14 (E_EXP * TWO_F * D_DIM / 4)
#define NW24 (E_EXP * D_DIM * F_DIM / 4)
__global__ void cvt_all_kernel(const float4* __restrict__ x,
                               const float4* __restrict__ w1,
                               const float4* __restrict__ w2) {
    int i = blockIdx.x * blockDim.x + threadIdx.x;
    if (i < NW14) {
        ((uint2*)g_w1h)[i] = cvth4(w1[i]);
    } else if (i < NW14 + NW24) {
        int j = i - NW14;
        ((uint2*)g_w2h)[j] = cvth4(w2[j]);
    } else if (i < NW14 + NW24 + NX4) {
        int j = i - NW14 - NW24;
        ((uint2*)g_xf)[j] = cvth4(x[j]);
    }
}

// ---------------- kernel 1: gate + top2 + routing ----------------
__global__ void gate_kernel(const float* __restrict__ x, const float* __restrict__ gw) {
    int warp = threadIdx.x >> 5;
    int lane = threadIdx.x & 31;
    int t = blockIdx.x * 4 + warp;
    float acc[8] = {0.f,0.f,0.f,0.f,0.f,0.f,0.f,0.f};
    const float* xr = x + (size_t)t * D_DIM;
    for (int d = lane; d < D_DIM; d += 32) {
        float xv = xr[d];
        const float* g = gw + d * 8;
        #pragma unroll
        for (int e = 0; e < 8; e++) acc[e] += xv * g[e];
    }
    #pragma unroll
    for (int off = 16; off > 0; off >>= 1)
        #pragma unroll
        for (int e = 0; e < 8; e++)
            acc[e] += __shfl_down_sync(0xffffffffu, acc[e], off);
    if (lane == 0) {
        int b0 = 0; float v0 = acc[0];
        #pragma unroll
        for (int e = 1; e < 8; e++) if (acc[e] > v0) { v0 = acc[e]; b0 = e; }
        int b1 = -1; float v1 = -3.4e38f;
        #pragma unroll
        for (int e = 0; e < 8; e++) if (e != b0 && acc[e] > v1) { v1 = acc[e]; b1 = e; }
        float w0 = 1.0f / (1.0f + expf(v1 - v0));
        g_wts[t][0] = w0;
        g_wts[t][1] = 1.0f - w0;
        int p0 = atomicAdd(&g_cnt[b0], 1);
        g_entries[b0][p0] = t * 2 + 0;
        int p1 = atomicAdd(&g_cnt[b1], 1);
        g_entries[b1][p1] = t * 2 + 1;
    }
}

// ---------------- shared GEMM machinery ----------------
// CTA tile 128(M) x 128(N); 8 warps, warp tile 32(M) x 64(N); 2 CTAs/SM.
// smem: [0..512) s_tok, [512..1024) s_val, tiles @1024: stage{0..2} x {A, B}
__device__ __forceinline__ void stage_load(
    uint32_t sb, int buf, int k0, int tid,
    const int* s_tok, bool a_is_pair,
    const __half* A, int lda,
    const __half* B, size_t brow0, int ldb)
{
    uint32_t base = sb + 1024 + buf * STAGE_BYTES;
    #pragma unroll
    for (int ii = 0; ii < 8; ii++) {
        int i = tid + ii * NTHREADS;     // [0, 2048)
        if (i < 1024) {                  // A: 128 rows x 8 vec16
            int r = i >> 3, v = i & 7;
            uint32_t dsw = sw128((uint32_t)(r * 128 + v * 16));
            int ts = s_tok[r];
            size_t ar = (size_t)(a_is_pair ? (ts >> 1) : ts) * lda + k0 + v * 8;
            cp16(base + dsw, A + ar);
        } else {                         // B: 128 rows x 8 vec16
            int j = i - 1024;
            int r = j >> 3, v = j & 7;
            uint32_t dsw = sw128((uint32_t)(r * 128 + v * 16));
            size_t wr = (brow0 + r) * (size_t)ldb + k0 + v * 8;
            cp16(base + A_TILE_BYTES + dsw, B + wr);
        }
    }
    CP_COMMIT();
}

// warp tile 32(M) x 64(N): per k16 step 6 ldsm4, 16 MMAs; each acc written
// once per step -> dependent writes 16 MMAs apart.
__device__ __forceinline__ void stage_compute(
    uint32_t sb, int buf, int wm, int wn, int lane, float acc[2][8][4])
{
    uint32_t base = sb + 1024 + buf * STAGE_BYTES;
    uint32_t lrow = lane & 15, lk = (lane >> 4) * 16;
    uint32_t ar0 = (uint32_t)(wm * 32 + 0  + lrow) * 128 + lk;
    uint32_t ar1 = (uint32_t)(wm * 32 + 16 + lrow) * 128 + lk;
    uint32_t br[4];
    #pragma unroll
    for (int np = 0; np < 4; np++)
        br[np] = (uint32_t)(wn * 64 + np * 16 + lrow) * 128 + lk;

    #pragma unroll
    for (int ks = 0; ks < 4; ks++) {
        uint32_t kb = ks * 32;
        uint32_t a[2][4], b[4][4];
        ldsm4(a[0], base + sw128(ar0 + kb));
        ldsm4(a[1], base + sw128(ar1 + kb));
        #pragma unroll
        for (int np = 0; np < 4; np++)
            ldsm4(b[np], base + A_TILE_BYTES + sw128(br[np] + kb));
        #pragma unroll
        for (int mt = 0; mt < 2; mt++)
            #pragma unroll
            for (int np = 0; np < 4; np++) {
                mma16816(acc[mt][2*np],   a[mt], b[np][0], b[np][2]);
                mma16816(acc[mt][2*np+1], a[mt], b[np][1], b[np][3]);
            }
    }
}

// ---------------- kernel 2: dense1 (fp16) + swiglu -> h fp16 ----------------
__global__ __launch_bounds__(NTHREADS, 2) void dense1_mma(const float* __restrict__ b1) {
    int e = blockIdx.z, rt = blockIdx.y, ct = blockIdx.x;
    int n = g_cnt[e];
    if (rt * TM >= n) return;

    extern __shared__ char smem[];
    int* s_tok = (int*)smem;
    int* s_val = (int*)(smem + 512);
    uint32_t sb = smem_u32(smem);
    int tid = threadIdx.x, lane = tid & 31, wid = tid >> 5;
    int wm = wid >> 1, wn = wid & 1;

    if (tid < TM) {
        int rg = rt * TM + tid;
        int cl = rg < n ? rg : n - 1;
        s_tok[tid] = g_entries[e][cl];
        s_val[tid] = rg < n;
    }
    __syncthreads();

    float acc[2][8][4];
    #pragma unroll
    for (int a = 0; a < 2; a++)
        #pragma unroll
        for (int b = 0; b < 8; b++)
            #pragma unroll
            for (int c = 0; c < 4; c++) acc[a][b][c] = 0.f;

    size_t brow0 = (size_t)e * TWO_F + (size_t)ct * TN;
    const int NS = D_DIM / KB;  // 16
    stage_load(sb, 0, 0, tid, s_tok, true, g_xf, D_DIM, g_w1h, brow0, D_DIM);
    stage_load(sb, 1, KB, tid, s_tok, true, g_xf, D_DIM, g_w1h, brow0, D_DIM);
    for (int s = 0; s < NS; s++) {
        if (s + 1 < NS) { CP_WAIT(1); } else { CP_WAIT(0); }
        __syncthreads();
        if (s + 2 < NS)
            stage_load(sb, (s + 2) % NSTAGE, (s + 2) * KB, tid, s_tok, true,
                       g_xf, D_DIM, g_w1h, brow0, D_DIM);
        stage_compute(sb, s % NSTAGE, wm, wn, lane, acc);
    }

    // epilogue: swiglu on (gate, value) adjacent even/odd cols
    #pragma unroll
    for (int mt = 0; mt < 2; mt++) {
        #pragma unroll
        for (int nt = 0; nt < 8; nt++) {
            int c = ct * TN + wn * 64 + nt * 8 + (lane & 3) * 2;
            float bg = b1[e * TWO_F + c];
            float bv = b1[e * TWO_F + c + 1];
            #pragma unroll
            for (int hrow = 0; hrow < 2; hrow++) {
                int r = wm * 32 + mt * 16 + (lane >> 2) + hrow * 8;
                if (!s_val[r]) continue;
                int ts = s_tok[r];
                float gpre = acc[mt][nt][hrow * 2 + 0] + bg;
                float vpre = acc[mt][nt][hrow * 2 + 1] + bv;
                float gg = fminf(gpre, 9.0f);
                float vv = fminf(fmaxf(vpre, -9.0f), 9.0f);
                float h = gg * (1.0f / (1.0f + expf(-1.702f * gg))) * (vv + 1.0f);
                g_hf[(size_t)ts * F_DIM + (c >> 1)] = __float2half_rn(h);
            }
        }
    }
}

// ---------------- kernel 3: dense2 (fp16) + bias + scale + atomic combine ----------------
__global__ __launch_bounds__(NTHREADS, 2) void dense2_mma(const float* __restrict__ b2,
                                                          float* __restrict__ out) {
    int e = blockIdx.z, rt = blockIdx.y, ct = blockIdx.x;
    int n = g_cnt[e];
    if (rt * TM >= n) return;

    extern __shared__ char smem[];
    int* s_tok = (int*)smem;
    int* s_val = (int*)(smem + 512);
    uint32_t sb = smem_u32(smem);
    int tid = threadIdx.x, lane = tid & 31, wid = tid >> 5;
    int wm = wid >> 1, wn = wid & 1;

    if (tid < TM) {
        int rg = rt * TM + tid;
        int cl = rg < n ? rg : n - 1;
        s_tok[tid] = g_entries[e][cl];
        s_val[tid] = rg < n;
    }
    __syncthreads();

    float acc[2][8][4];
    #pragma unroll
    for (int a = 0; a < 2; a++)
        #pragma unroll
        for (int b = 0; b < 8; b++)
            #pragma unroll
            for (int c = 0; c < 4; c++) acc[a][b][c] = 0.f;

    size_t brow0 = (size_t)e * D_DIM + (size_t)ct * TN;
    const int NS = F_DIM / KB;  // 32
    stage_load(sb, 0, 0, tid, s_tok, false, g_hf, F_DIM, g_w2h, brow0, F_DIM);
    stage_load(sb, 1, KB, tid, s_tok, false, g_hf, F_DIM, g_w2h, brow0, F_DIM);
    for (int s = 0; s < NS; s++) {
        if (s + 1 < NS) { CP_WAIT(1); } else { CP_WAIT(0); }
        __syncthreads();
        if (s + 2 < NS)
            stage_load(sb, (s + 2) % NSTAGE, (s + 2) * KB, tid, s_tok, false,
                       g_hf, F_DIM, g_w2h, brow0, F_DIM);
        stage_compute(sb, s % NSTAGE, wm, wn, lane, acc);
    }

    // per output element exactly 2 expert contributions; fp32 atomicAdd onto
    // zeroed out is commutative -> deterministic.
    #pragma unroll
    for (int mt = 0; mt < 2; mt++) {
        #pragma unroll
        for (int hrow = 0; hrow < 2; hrow++) {
            int r = wm * 32 + mt * 16 + (lane >> 2) + hrow * 8;
            if (!s_val[r]) continue;
            int ts = s_tok[r];
            float wgt = g_wts[ts >> 1][ts & 1];
            float* yrow = out + (size_t)(ts >> 1) * D_DIM;
            #pragma unroll
            for (int nt = 0; nt < 8; nt++) {
                int c = ct * TN + wn * 64 + nt * 8 + (lane & 3) * 2;
                atomicAdd(yrow + c,     (acc[mt][nt][hrow * 2 + 0] + b2[e * D_DIM + c]) * wgt);
                atomicAdd(yrow + c + 1, (acc[mt][nt][hrow * 2 + 1] + b2[e * D_DIM + c + 1]) * wgt);
            }
        }
    }
}

// ---------------- launch ----------------
extern "C" void kernel_launch(void* const* d_in, const int* in_sizes, int n_in,
                              void* d_out, int out_size) {
    const float* x  = (const float*)d_in[0];
    const float* gw = (const float*)d_in[1];
    const float* w1 = (const float*)d_in[2];
    const float* b1 = (const float*)d_in[3];
    const float* w2 = (const float*)d_in[4];
    const float* b2 = (const float*)d_in[5];
    float* out = (float*)d_out;

    cudaFuncSetAttribute(dense1_mma, cudaFuncAttributeMaxDynamicSharedMemorySize, SMEM_BYTES);
    cudaFuncSetAttribute(dense2_mma, cudaFuncAttributeMaxDynamicSharedMemorySize, SMEM_BYTES);

    zero_all_kernel<<<(T_TOKENS * D_DIM / 4 + 255) / 256, 256>>>((float4*)out);
    cvt_all_kernel<<<(NW14 + NW24 + NX4 + 255) / 256, 256>>>(
        (const float4*)x, (const float4*)w1, (const float4*)w2);
    gate_kernel<<<T_TOKENS / 4, 128>>>(x, gw);
    dense1_mma<<<dim3(TWO_F / TN, T_TOKENS / TM, E_EXP), NTHREADS, SMEM_BYTES>>>(b1);
    dense2_mma<<<dim3(D_DIM / TN, T_TOKENS / TM, E_EXP), NTHREADS, SMEM_BYTES>>>(b2, out);
}